// round 13
// baseline (speedup 1.0000x reference)
#include <cuda_runtime.h>
#include <cuda_fp16.h>
#include <cstdint>

#define BATCH 16
#define CIN   128
#define COUT  256
#define HW    56

__device__ __align__(16) __half g_xh[BATCH * HW * HW * CIN]; // NHWC fp16 (12.8MB)
__device__ __align__(16) __half g_wh[9 * COUT * CIN];        // [tap][o][c] fp16

__device__ __forceinline__ uint32_t smem_u32(const void* p) {
    uint32_t a;
    asm("{ .reg .u64 t; cvta.to.shared.u64 t, %1; cvt.u32.u64 %0, t; }" : "=r"(a) : "l"(p));
    return a;
}

// ---------------------------------------------------------------------------
// Kernel 1: x NCHW f32 -> NHWC fp16 quantized. 64 ch per CTA, 128 threads ->
// 7 independent float4 loads per thread (MLP 7) to cover DRAM latency.
// ---------------------------------------------------------------------------
__global__ void __launch_bounds__(128) pack_x_kernel(const float* __restrict__ x) {
    __shared__ float tile[64][60];
    const int b = blockIdx.x / HW, h = blockIdx.x % HW;
    const int ch0 = blockIdx.y * 64;
    const int t = threadIdx.x;
#pragma unroll
    for (int j = 0; j < 7; ++j) {              // 896 float4 loads, 7/thread
        int idx = t + j * 128;
        int c = idx / 14, f4 = idx % 14;
        float4 v = *(const float4*)&x[((b * CIN + ch0 + c) * HW + h) * HW + f4 * 4];
        tile[c][f4 * 4 + 0] = v.x; tile[c][f4 * 4 + 1] = v.y;
        tile[c][f4 * 4 + 2] = v.z; tile[c][f4 * 4 + 3] = v.w;
    }
    __syncthreads();
#pragma unroll
    for (int j = 0; j < 4; ++j) {              // 448 = 8 chunks * 56 w, w-major
        int i = t + j * 128;
        if (i >= HW * 8) break;
        int chunk = i / HW, w = i % HW;
        int c0 = chunk * 8;
        uint4 vv;
        unsigned* pv = (unsigned*)&vv;
#pragma unroll
        for (int k = 0; k < 4; ++k) {
            float q0 = rintf(tile[c0 + 2 * k][w] * 255.0f);
            float q1 = rintf(tile[c0 + 2 * k + 1][w] * 255.0f);
            q0 = fminf(fmaxf(q0, 0.0f), 255.0f);
            q1 = fminf(fmaxf(q1, 0.0f), 255.0f);
            __half2 h2 = __floats2half2_rn(q0, q1);
            pv[k] = *(unsigned*)&h2;
        }
        *(uint4*)&g_xh[((b * HW + h) * HW + w) * CIN + ch0 + c0] = vv;
    }
}

// ---------------------------------------------------------------------------
// Kernel 2: pcilt[...,1] -> [tap][o][c] fp16
// ---------------------------------------------------------------------------
__global__ void pack_w_kernel(const float* __restrict__ pcilt) {
    int idx = blockIdx.x * 256 + threadIdx.x;
    if (idx >= 9 * COUT * CIN) return;
    int c   = idx % CIN;
    int o   = (idx / CIN) % COUT;
    int tap = idx / (CIN * COUT);
    long long p = (((long long)(o * CIN + c)) * 9 + tap) * 256 + 1;
    g_wh[(tap * COUT + o) * CIN + c] = __float2half_rn(pcilt[p]);
}

// ---------------------------------------------------------------------------
// Kernel 3: role-swapped HMMA implicit-GEMM conv, 12 warps (3/SMSP).
//   A (M=128) = oc; B (N=112) = pixels via per-lane ldmatrix addresses.
//   Warp tiles 32oc x {40,40,32}px. 3-slot W ring, distance-2 producer wait.
// ---------------------------------------------------------------------------
#define PXS       272
#define X_PX      232
#define WST       272
#define SMEM_SX   0
#define SMEM_W0   (X_PX * PXS)                     // 63104
#define W_SLOT_SZ (128 * WST)                      // 34816
#define SMEM_MB   (SMEM_W0 + 3 * W_SLOT_SZ)        // 167552
#define SMEM_SZ   (SMEM_MB + 64)
#define NTHR      384

__device__ __forceinline__ void hmma(float* c, unsigned a0, unsigned a1, unsigned a2, unsigned a3,
                                     unsigned b0, unsigned b1) {
    asm volatile(
        "mma.sync.aligned.m16n8k16.row.col.f32.f16.f16.f32 "
        "{%0,%1,%2,%3}, {%4,%5,%6,%7}, {%8,%9}, {%0,%1,%2,%3};"
        : "+f"(c[0]), "+f"(c[1]), "+f"(c[2]), "+f"(c[3])
        : "r"(a0), "r"(a1), "r"(a2), "r"(a3), "r"(b0), "r"(b1));
}
#define LDSM4(r0, r1, r2, r3, addr) \
    asm volatile("ldmatrix.sync.aligned.m8n8.x4.shared.b16 {%0,%1,%2,%3}, [%4];" \
        : "=r"(r0), "=r"(r1), "=r"(r2), "=r"(r3) : "r"(addr))
#define LDSM2(r0, r1, addr) \
    asm volatile("ldmatrix.sync.aligned.m8n8.x2.shared.b16 {%0,%1}, [%2];" \
        : "=r"(r0), "=r"(r1) : "r"(addr))
#define CPASYNC(dst, src, sz) \
    asm volatile("cp.async.cg.shared.global [%0], [%1], 16, %2;" :: "r"(dst), "l"(src), "r"(sz))
#define MBAR_INIT(a, n) asm volatile("mbarrier.init.shared.b64 [%0], %1;" :: "r"(a), "r"(n) : "memory")
#define MBAR_ARRIVE(a)  asm volatile("mbarrier.arrive.shared.b64 _, [%0];" :: "r"(a) : "memory")
#define CP_MBAR_ARRIVE(a) \
    asm volatile("cp.async.mbarrier.arrive.noinc.shared.b64 [%0];" :: "r"(a) : "memory")
#define MBAR_WAIT(a, ph) do {                                                     \
    uint32_t _m = (a), _p = (uint32_t)(ph), _d;                                   \
    asm volatile("{ .reg .pred p; mbarrier.try_wait.parity.acquire.cta.shared::cta.b64 p, [%1], %2; selp.b32 %0,1,0,p; }" \
        : "=r"(_d) : "r"(_m), "r"(_p) : "memory");                                \
    if (!_d) {                                                                    \
        asm volatile("{ .reg .pred P1; WL_%=: mbarrier.try_wait.parity.acquire.cta.shared::cta.b64 P1, [%0], %1, 0x989680;" \
            " @P1 bra.uni WD_%=; bra.uni WL_%=; WD_%=: }" :: "r"(_m), "r"(_p) : "memory"); \
    } } while (0)

template<int NT>
__device__ __forceinline__ void conv_mainloop(
    uint32_t sb, int t, int ocbase, uint32_t a_off,
    uint32_t bp0, uint32_t bp1, uint32_t bp2,
    const __half* __restrict__ gw, float acc[2][5][4])
{
    const uint32_t mb_full  = sb + SMEM_MB;
    const uint32_t mb_empty = sb + SMEM_MB + 24;
    int slot = 0, cons_ph = 0;

#pragma unroll 1
    for (int tap = 0; tap < 9; ++tap) {
        const int kh = tap / 3, kw = tap % 3;
        const uint32_t aw = sb + SMEM_W0 + slot * W_SLOT_SZ + a_off;
        const uint32_t toff = (uint32_t)(kh * 58 + kw) * PXS;

        MBAR_WAIT(mb_full + slot * 8, cons_ph);

        unsigned a[2][2][4], bf[2][5][2];
        LDSM4(a[0][0][0], a[0][0][1], a[0][0][2], a[0][0][3], aw);
        LDSM4(a[0][1][0], a[0][1][1], a[0][1][2], a[0][1][3], aw + 16 * WST);
        LDSM4(bf[0][0][0], bf[0][0][1], bf[0][1][0], bf[0][1][1], bp0 + toff);
        LDSM4(bf[0][2][0], bf[0][2][1], bf[0][3][0], bf[0][3][1], bp1 + toff);
        if (NT == 5) LDSM2(bf[0][4][0], bf[0][4][1], bp2 + toff);

#pragma unroll
        for (int ks = 0; ks < 8; ++ks) {
            const int cur = ks & 1, nxt = cur ^ 1;
            if (ks < 7) {
                const int koff = (ks + 1) * 32;
                LDSM4(a[nxt][0][0], a[nxt][0][1], a[nxt][0][2], a[nxt][0][3], aw + koff);
                LDSM4(a[nxt][1][0], a[nxt][1][1], a[nxt][1][2], a[nxt][1][3],
                      aw + 16 * WST + koff);
                LDSM4(bf[nxt][0][0], bf[nxt][0][1], bf[nxt][1][0], bf[nxt][1][1],
                      bp0 + toff + koff);
                LDSM4(bf[nxt][2][0], bf[nxt][2][1], bf[nxt][3][0], bf[nxt][3][1],
                      bp1 + toff + koff);
                if (NT == 5) LDSM2(bf[nxt][4][0], bf[nxt][4][1], bp2 + toff + koff);
            }
#pragma unroll
            for (int mt = 0; mt < 2; ++mt)
#pragma unroll
                for (int nt = 0; nt < NT; ++nt)
                    hmma(acc[mt][nt], a[cur][mt][0], a[cur][mt][1], a[cur][mt][2], a[cur][mt][3],
                         bf[cur][nt][0], bf[cur][nt][1]);
        }

        MBAR_ARRIVE(mb_empty + slot * 8);

        if (tap >= 1 && tap <= 6) {
            const int ws = (slot + 2 >= 3) ? slot - 1 : slot + 2;
            const int pph = ((tap - 1) / 3) & 1;
            MBAR_WAIT(mb_empty + ws * 8, pph);
            uint32_t wdst = sb + SMEM_W0 + ws * W_SLOT_SZ;
            for (int i = t; i < 128 * 16; i += NTHR) {
                int o = i >> 4, chunk = i & 15;
                CPASYNC(wdst + o * WST + chunk * 16,
                        &gw[((tap + 2) * COUT + ocbase + o) * CIN + chunk * 8], 16);
            }
            CP_MBAR_ARRIVE(mb_full + ws * 8);
        }

        slot = (slot + 1 == 3) ? 0 : slot + 1;
        if (tap == 2 || tap == 5) cons_ph ^= 1;
    }
}

__global__ void __launch_bounds__(NTHR, 1)
conv_hmma_kernel(const float* __restrict__ bias, float* __restrict__ out) {
    extern __shared__ __align__(16) unsigned char smem[];
    const uint32_t sb = smem_u32(smem);

    const int t    = threadIdx.x;
    const int wid  = t >> 5;
    const int lane = t & 31;
    const int ocbase = blockIdx.x * 128;
    const int h0     = blockIdx.y * 2;
    const int b      = blockIdx.z;

    const uint32_t mb_full  = sb + SMEM_MB;
    const uint32_t mb_empty = sb + SMEM_MB + 24;

    if (t == 0) {
#pragma unroll
        for (int s = 0; s < 3; ++s) {
            MBAR_INIT(mb_full + s * 8, NTHR);
            MBAR_INIT(mb_empty + s * 8, NTHR);
        }
    }
    __syncthreads();

    // ---- Prologue: X halo tile + W taps 0,1,2 into slots 0,1,2 ----
    for (int i = t; i < X_PX * 16; i += NTHR) {
        int px = i >> 4, chunk = i & 15;
        int row = px / 58, col = px % 58;
        int h_in = h0 + row - 1, w_in = col - 1;
        bool ok = (h_in >= 0) && (h_in < HW) && (w_in >= 0) && (w_in < HW);
        const __half* src = ok ? &g_xh[((b * HW + h_in) * HW + w_in) * CIN + chunk * 8] : g_xh;
        CPASYNC(sb + SMEM_SX + px * PXS + chunk * 16, src, ok ? 16 : 0);
    }
#pragma unroll
    for (int tap = 0; tap < 3; ++tap) {
        uint32_t wdst = sb + SMEM_W0 + tap * W_SLOT_SZ;
        for (int i = t; i < 128 * 16; i += NTHR) {
            int o = i >> 4, chunk = i & 15;
            CPASYNC(wdst + o * WST + chunk * 16,
                    &g_wh[(tap * COUT + ocbase + o) * CIN + chunk * 8], 16);
        }
        CP_MBAR_ARRIVE(mb_full + tap * 8);
    }

    // Warp tiling: 4 (M, 32 oc) x 3 (N, 40/40/32 px)
    const int wm_i = wid & 3;                // 0..3
    const int wn_i = wid >> 2;               // 0..2
    const int wm = wm_i * 32;
    const int wn = wn_i * 40;

    float acc[2][5][4];
#pragma unroll
    for (int mt = 0; mt < 2; ++mt)
#pragma unroll
        for (int nt = 0; nt < 5; ++nt)
#pragma unroll
            for (int k = 0; k < 4; ++k) acc[mt][nt][k] = 0.0f;

    const int g = lane >> 3;
    const uint32_t a_off = (uint32_t)(wm + ((g & 1) * 8) + (lane & 7)) * WST + (g >> 1) * 16;
    auto px_addr = [&](int px) -> uint32_t {
        int r = px / 56, w = px % 56;
        return sb + SMEM_SX + (uint32_t)(r * 58 + w) * PXS;
    };
    const int pxl = (lane & 7);
    const uint32_t bp0 = px_addr(wn + ((g >> 1) + 0) * 8 + pxl) + (g & 1) * 16;
    const uint32_t bp1 = px_addr(wn + ((g >> 1) + 2) * 8 + pxl) + (g & 1) * 16;
    // LDSM2 (tile 4): lanes 0-15 supply addresses; keep others in-range.
    const uint32_t bp2 = px_addr(wn + ((wn_i < 2) ? 32 : 0) + pxl) + ((lane >> 3) & 1) * 16;

    if (wn_i < 2)
        conv_mainloop<5>(sb, t, ocbase, a_off, bp0, bp1, bp2, g_wh, acc);
    else
        conv_mainloop<4>(sb, t, ocbase, a_off, bp0, bp1, bp2, g_wh, acc);

    // ---- Epilogue: direct NCHW float2 stores ----
    const int NT = (wn_i < 2) ? 5 : 4;
#pragma unroll
    for (int mt = 0; mt < 2; ++mt) {
        const int oc0 = ocbase + wm + mt * 16 + (lane >> 2);
        const float bv0 = bias[oc0];
        const float bv8 = bias[oc0 + 8];
#pragma unroll
        for (int nt = 0; nt < 5; ++nt) {
            if (nt >= NT) break;
            const int px = wn + nt * 8 + (lane & 3) * 2;
            const int r = px / 56, w = px % 56;
            const int hrow = h0 + r;
            float* p0 = out + (((long long)b * COUT + oc0) * HW + hrow) * HW;
            float* p8 = out + (((long long)b * COUT + oc0 + 8) * HW + hrow) * HW;
            float2 v0 = make_float2(acc[mt][nt][0] + bv0, acc[mt][nt][1] + bv0);
            float2 v8 = make_float2(acc[mt][nt][2] + bv8, acc[mt][nt][3] + bv8);
            *(float2*)(p0 + w) = v0;
            *(float2*)(p8 + w) = v8;
        }
    }
}

// ---------------------------------------------------------------------------
extern "C" void kernel_launch(void* const* d_in, const int* in_sizes, int n_in,
                              void* d_out, int out_size) {
    const float* x = nullptr;
    const float* pcilt = nullptr;
    const float* bias = nullptr;
    for (int i = 0; i < n_in; ++i) {
        if (in_sizes[i] == COUT) bias = (const float*)d_in[i];
        else if (in_sizes[i] == BATCH * CIN * HW * HW) x = (const float*)d_in[i];
        else pcilt = (const float*)d_in[i];
    }
    float* out = (float*)d_out;

    {
        dim3 g(BATCH * HW, 2);
        pack_x_kernel<<<g, 128>>>(x);
    }
    {
        int n = 9 * COUT * CIN;
        pack_w_kernel<<<(n + 255) / 256, 256>>>(pcilt);
    }
    {
        cudaFuncSetAttribute(conv_hmma_kernel,
                             cudaFuncAttributeMaxDynamicSharedMemorySize, SMEM_SZ);
        dim3 grid(COUT / 128, HW / 2, BATCH);   // (2, 28, 16) = 896 CTAs
        conv_hmma_kernel<<<grid, NTHR, SMEM_SZ>>>(bias, out);
    }
    (void)out_size;
}

// round 14
// speedup vs baseline: 1.1125x; 1.1125x over previous
#include <cuda_runtime.h>
#include <cuda_fp16.h>
#include <cstdint>

#define BATCH 16
#define CIN   128
#define COUT  256
#define HW    56

__device__ __align__(16) __half g_xh[BATCH * HW * HW * CIN]; // NHWC fp16 (12.8MB)
__device__ __align__(16) __half g_wh[9 * COUT * CIN];        // [tap][o][c] fp16

__device__ __forceinline__ uint32_t smem_u32(const void* p) {
    uint32_t a;
    asm("{ .reg .u64 t; cvta.to.shared.u64 t, %1; cvt.u32.u64 %0, t; }" : "=r"(a) : "l"(p));
    return a;
}

// ---------------------------------------------------------------------------
// Kernel 1: x NCHW f32 -> NHWC fp16 quantized (R10/R12 proven version)
// ---------------------------------------------------------------------------
__global__ void __launch_bounds__(128) pack_x_kernel(const float* __restrict__ x) {
    __shared__ float tile[32][60];
    const int b = blockIdx.x / HW, h = blockIdx.x % HW;
    const int ch0 = blockIdx.y * 32;
    const int t = threadIdx.x;
#pragma unroll
    for (int j = 0; j < 4; ++j) {
        int idx = t + j * 128;
        if (idx >= 32 * 14) break;
        int c = idx / 14, f4 = idx % 14;
        float4 v = *(const float4*)&x[((b * CIN + ch0 + c) * HW + h) * HW + f4 * 4];
        tile[c][f4 * 4 + 0] = v.x; tile[c][f4 * 4 + 1] = v.y;
        tile[c][f4 * 4 + 2] = v.z; tile[c][f4 * 4 + 3] = v.w;
    }
    __syncthreads();
#pragma unroll
    for (int j = 0; j < 2; ++j) {
        int i = t + j * 128;
        if (i >= HW * 4) break;
        int chunk = i / HW, w = i % HW;
        int c0 = chunk * 8;
        uint4 vv;
        unsigned* pv = (unsigned*)&vv;
#pragma unroll
        for (int k = 0; k < 4; ++k) {
            float q0 = rintf(tile[c0 + 2 * k][w] * 255.0f);
            float q1 = rintf(tile[c0 + 2 * k + 1][w] * 255.0f);
            q0 = fminf(fmaxf(q0, 0.0f), 255.0f);
            q1 = fminf(fmaxf(q1, 0.0f), 255.0f);
            __half2 h2 = __floats2half2_rn(q0, q1);
            pv[k] = *(unsigned*)&h2;
        }
        *(uint4*)&g_xh[((b * HW + h) * HW + w) * CIN + ch0 + c0] = vv;
    }
}

// ---------------------------------------------------------------------------
// Kernel 2: pcilt[...,1] -> [tap][o][c] fp16
// ---------------------------------------------------------------------------
__global__ void pack_w_kernel(const float* __restrict__ pcilt) {
    int idx = blockIdx.x * 256 + threadIdx.x;
    if (idx >= 9 * COUT * CIN) return;
    int c   = idx % CIN;
    int o   = (idx / CIN) % COUT;
    int tap = idx / (CIN * COUT);
    long long p = (((long long)(o * CIN + c)) * 9 + tap) * 256 + 1;
    g_wh[(tap * COUT + o) * CIN + c] = __float2half_rn(pcilt[p]);
}

// ---------------------------------------------------------------------------
// Kernel 3: role-swapped HMMA conv, SMALL CTA for 2 CTAs/SM.
//   CTA = M64 oc x N112 px, 4 warps (32oc x 56px). 2-slot W ring.
//   Smem 98KB -> 2 CTAs/SM: halved wave tail + cross-CTA overlap.
// ---------------------------------------------------------------------------
#define PXS       272
#define X_PX      232                              // 4 input rows x 58 cols
#define WST       272
#define SMEM_SX   0
#define SMEM_W0   (X_PX * PXS)                     // 63104
#define W_SLOT_SZ (64 * WST)                       // 17408
#define SMEM_MB   (SMEM_W0 + 2 * W_SLOT_SZ)        // 97920
#define SMEM_SZ   (SMEM_MB + 64)                   // 97984
#define NTHR      128

__device__ __forceinline__ void hmma(float* c, unsigned a0, unsigned a1, unsigned a2, unsigned a3,
                                     unsigned b0, unsigned b1) {
    asm volatile(
        "mma.sync.aligned.m16n8k16.row.col.f32.f16.f16.f32 "
        "{%0,%1,%2,%3}, {%4,%5,%6,%7}, {%8,%9}, {%0,%1,%2,%3};"
        : "+f"(c[0]), "+f"(c[1]), "+f"(c[2]), "+f"(c[3])
        : "r"(a0), "r"(a1), "r"(a2), "r"(a3), "r"(b0), "r"(b1));
}
#define LDSM4(r0, r1, r2, r3, addr) \
    asm volatile("ldmatrix.sync.aligned.m8n8.x4.shared.b16 {%0,%1,%2,%3}, [%4];" \
        : "=r"(r0), "=r"(r1), "=r"(r2), "=r"(r3) : "r"(addr))
#define LDSM2(r0, r1, addr) \
    asm volatile("ldmatrix.sync.aligned.m8n8.x2.shared.b16 {%0,%1}, [%2];" \
        : "=r"(r0), "=r"(r1) : "r"(addr))
#define CPASYNC(dst, src, sz) \
    asm volatile("cp.async.cg.shared.global [%0], [%1], 16, %2;" :: "r"(dst), "l"(src), "r"(sz))
#define MBAR_INIT(a, n) asm volatile("mbarrier.init.shared.b64 [%0], %1;" :: "r"(a), "r"(n) : "memory")
#define MBAR_ARRIVE(a)  asm volatile("mbarrier.arrive.shared.b64 _, [%0];" :: "r"(a) : "memory")
#define CP_MBAR_ARRIVE(a) \
    asm volatile("cp.async.mbarrier.arrive.noinc.shared.b64 [%0];" :: "r"(a) : "memory")
#define MBAR_WAIT(a, ph) do {                                                     \
    uint32_t _m = (a), _p = (uint32_t)(ph), _d;                                   \
    asm volatile("{ .reg .pred p; mbarrier.try_wait.parity.acquire.cta.shared::cta.b64 p, [%1], %2; selp.b32 %0,1,0,p; }" \
        : "=r"(_d) : "r"(_m), "r"(_p) : "memory");                                \
    if (!_d) {                                                                    \
        asm volatile("{ .reg .pred P1; WL_%=: mbarrier.try_wait.parity.acquire.cta.shared::cta.b64 P1, [%0], %1, 0x989680;" \
            " @P1 bra.uni WD_%=; bra.uni WL_%=; WD_%=: }" :: "r"(_m), "r"(_p) : "memory"); \
    } } while (0)

__global__ void __launch_bounds__(NTHR, 2)
conv_hmma_kernel(const float* __restrict__ bias, float* __restrict__ out) {
    extern __shared__ __align__(16) unsigned char smem[];
    const uint32_t sb = smem_u32(smem);

    const int t    = threadIdx.x;
    const int wid  = t >> 5;
    const int lane = t & 31;
    const int ocbase = blockIdx.x * 64;       // 4 oc tiles
    const int h0     = blockIdx.y * 2;
    const int b      = blockIdx.z;

    const uint32_t mb_full  = sb + SMEM_MB;        // 2 x 8B
    const uint32_t mb_empty = sb + SMEM_MB + 16;   // 2 x 8B

    if (t == 0) {
#pragma unroll
        for (int s = 0; s < 2; ++s) {
            MBAR_INIT(mb_full + s * 8, NTHR);
            MBAR_INIT(mb_empty + s * 8, NTHR);
        }
    }
    __syncthreads();

    // ---- Prologue: X halo tile (232 px) + W taps 0,1 into slots 0,1 ----
    for (int i = t; i < X_PX * 16; i += NTHR) {
        int px = i >> 4, chunk = i & 15;
        int row = px / 58, col = px % 58;
        int h_in = h0 + row - 1, w_in = col - 1;
        bool ok = (h_in >= 0) && (h_in < HW) && (w_in >= 0) && (w_in < HW);
        const __half* src = ok ? &g_xh[((b * HW + h_in) * HW + w_in) * CIN + chunk * 8] : g_xh;
        CPASYNC(sb + SMEM_SX + px * PXS + chunk * 16, src, ok ? 16 : 0);
    }
#pragma unroll
    for (int tap = 0; tap < 2; ++tap) {
        uint32_t wdst = sb + SMEM_W0 + tap * W_SLOT_SZ;
#pragma unroll
        for (int j = 0; j < 8; ++j) {
            int i = t + j * NTHR;
            int o = i >> 4, chunk = i & 15;
            CPASYNC(wdst + o * WST + chunk * 16,
                    &g_wh[(tap * COUT + ocbase + o) * CIN + chunk * 8], 16);
        }
        CP_MBAR_ARRIVE(mb_full + tap * 8);
    }

    const int wm = (wid >> 1) * 32;          // warp oc offset (0/32)
    const int wn = (wid & 1) * 56;           // warp pixel offset (0/56)

    float acc[2][7][4];
#pragma unroll
    for (int mt = 0; mt < 2; ++mt)
#pragma unroll
        for (int nt = 0; nt < 7; ++nt)
#pragma unroll
            for (int k = 0; k < 4; ++k) acc[mt][nt][k] = 0.0f;

    const int g = lane >> 3;
    const uint32_t a_lane = (uint32_t)(wm + ((g & 1) * 8) + (lane & 7)) * WST + (g >> 1) * 16;
    auto px_addr = [&](int px) -> uint32_t {
        int r = px / 56, w = px % 56;
        return sb + SMEM_SX + (uint32_t)(r * 58 + w) * PXS;
    };
    const int pxl = (lane & 7);
    const uint32_t bp0 = px_addr(wn + ((g >> 1) + 0) * 8 + pxl) + (g & 1) * 16;
    const uint32_t bp1 = px_addr(wn + ((g >> 1) + 2) * 8 + pxl) + (g & 1) * 16;
    const uint32_t bp2 = px_addr(wn + ((g >> 1) + 4) * 8 + pxl) + (g & 1) * 16;
    const uint32_t bp3 = px_addr(wn + 48 + pxl) + ((lane >> 3) & 1) * 16;

#pragma unroll 1
    for (int tap = 0; tap < 9; ++tap) {
        const int kh = tap / 3, kw = tap % 3;
        const int slot = tap & 1;
        const uint32_t aw = sb + SMEM_W0 + slot * W_SLOT_SZ + a_lane;
        const uint32_t toff = (uint32_t)(kh * 58 + kw) * PXS;

        MBAR_WAIT(mb_full + slot * 8, (tap >> 1) & 1);

        unsigned a[2][2][4], bf[2][7][2];
        LDSM4(a[0][0][0], a[0][0][1], a[0][0][2], a[0][0][3], aw);
        LDSM4(a[0][1][0], a[0][1][1], a[0][1][2], a[0][1][3], aw + 16 * WST);
        LDSM4(bf[0][0][0], bf[0][0][1], bf[0][1][0], bf[0][1][1], bp0 + toff);
        LDSM4(bf[0][2][0], bf[0][2][1], bf[0][3][0], bf[0][3][1], bp1 + toff);
        LDSM4(bf[0][4][0], bf[0][4][1], bf[0][5][0], bf[0][5][1], bp2 + toff);
        LDSM2(bf[0][6][0], bf[0][6][1], bp3 + toff);

#pragma unroll
        for (int ks = 0; ks < 8; ++ks) {
            const int cur = ks & 1, nxt = cur ^ 1;
            if (ks < 7) {
                const int koff = (ks + 1) * 32;
                LDSM4(a[nxt][0][0], a[nxt][0][1], a[nxt][0][2], a[nxt][0][3], aw + koff);
                LDSM4(a[nxt][1][0], a[nxt][1][1], a[nxt][1][2], a[nxt][1][3],
                      aw + 16 * WST + koff);
                LDSM4(bf[nxt][0][0], bf[nxt][0][1], bf[nxt][1][0], bf[nxt][1][1],
                      bp0 + toff + koff);
                LDSM4(bf[nxt][2][0], bf[nxt][2][1], bf[nxt][3][0], bf[nxt][3][1],
                      bp1 + toff + koff);
                LDSM4(bf[nxt][4][0], bf[nxt][4][1], bf[nxt][5][0], bf[nxt][5][1],
                      bp2 + toff + koff);
                LDSM2(bf[nxt][6][0], bf[nxt][6][1], bp3 + toff + koff);
            }
#pragma unroll
            for (int mt = 0; mt < 2; ++mt)
#pragma unroll
                for (int nt = 0; nt < 7; ++nt)
                    hmma(acc[mt][nt], a[cur][mt][0], a[cur][mt][1], a[cur][mt][2], a[cur][mt][3],
                         bf[cur][nt][0], bf[cur][nt][1]);
        }

        MBAR_ARRIVE(mb_empty + slot * 8);

        // Prefetch tap+2 into the slot just consumed (rendezvous stall is
        // covered by the co-resident CTA).
        if (tap <= 6) {
            MBAR_WAIT(mb_empty + slot * 8, (tap >> 1) & 1);
            uint32_t wdst = sb + SMEM_W0 + slot * W_SLOT_SZ;
#pragma unroll
            for (int j = 0; j < 8; ++j) {
                int i = t + j * NTHR;
                int o = i >> 4, chunk = i & 15;
                CPASYNC(wdst + o * WST + chunk * 16,
                        &g_wh[((tap + 2) * COUT + ocbase + o) * CIN + chunk * 8], 16);
            }
            CP_MBAR_ARRIVE(mb_full + slot * 8);
        }
    }

    // ---- Epilogue: direct NCHW float2 stores ----
    const int r  = wid & 1;
    const int hrow = h0 + r;
#pragma unroll
    for (int mt = 0; mt < 2; ++mt) {
        const int oc0 = ocbase + wm + mt * 16 + (lane >> 2);
        const float bv0 = bias[oc0];
        const float bv8 = bias[oc0 + 8];
        float* p0 = out + (((long long)b * COUT + oc0) * HW + hrow) * HW;
        float* p8 = out + (((long long)b * COUT + oc0 + 8) * HW + hrow) * HW;
#pragma unroll
        for (int nt = 0; nt < 7; ++nt) {
            const int w = nt * 8 + (lane & 3) * 2;
            float2 v0 = make_float2(acc[mt][nt][0] + bv0, acc[mt][nt][1] + bv0);
            float2 v8 = make_float2(acc[mt][nt][2] + bv8, acc[mt][nt][3] + bv8);
            *(float2*)(p0 + w) = v0;
            *(float2*)(p8 + w) = v8;
        }
    }
}

// ---------------------------------------------------------------------------
extern "C" void kernel_launch(void* const* d_in, const int* in_sizes, int n_in,
                              void* d_out, int out_size) {
    const float* x = nullptr;
    const float* pcilt = nullptr;
    const float* bias = nullptr;
    for (int i = 0; i < n_in; ++i) {
        if (in_sizes[i] == COUT) bias = (const float*)d_in[i];
        else if (in_sizes[i] == BATCH * CIN * HW * HW) x = (const float*)d_in[i];
        else pcilt = (const float*)d_in[i];
    }
    float* out = (float*)d_out;

    {
        dim3 g(BATCH * HW, 4);
        pack_x_kernel<<<g, 128>>>(x);
    }
    {
        int n = 9 * COUT * CIN;
        pack_w_kernel<<<(n + 255) / 256, 256>>>(pcilt);
    }
    {
        cudaFuncSetAttribute(conv_hmma_kernel,
                             cudaFuncAttributeMaxDynamicSharedMemorySize, SMEM_SZ);
        dim3 grid(COUT / 64, HW / 2, BATCH);   // (4, 28, 16) = 1792 CTAs, 2/SM
        conv_hmma_kernel<<<grid, NTHR, SMEM_SZ>>>(bias, out);
    }
    (void)out_size;
}